// round 12
// baseline (speedup 1.0000x reference)
#include <cuda_runtime.h>
#include <math.h>
#include <stdint.h>

#define NT 1024
// ---- smem float offsets (all frag-contiguous layouts) ----
// quad panels: float4 idx = (i16*64 + kf)*8 + g, kf = (k>>3)*4 + (k&3)
//   comps: ((i>>3)&1) + 2*((k>>2)&1)
#define O_XQ  0        // x     8192 floats
#define O_X0Q 8192     // x0    8192
#define O_ZSQ 16384    // z_s   8192 (also raw-x0 staging [i*128+k] in prologue)
#define O_ZAQ 24576    // z_a   8192
#define O_XTB 32768    // x^T   f2 idx=(((d>>3)*2+jblk)*4+ks)*8+(d&7))*4+t, comp=(jl>>2)&1
#define O_WE3 40960    // we 3 layers x [same|anti] x [8][128] = 6144
#define O_R   47104
#define SMF   47360    // 189,440 B

__device__ float g_fq[512][32768];    // feat frag-quads (coalesced LDG.128 order)
__device__ float g_W2Q[3][65536];     // W2 frag-quads (coalesced LDG.128 order)

static __device__ __forceinline__ unsigned rna(float v) {
    unsigned u; asm("cvt.rna.tf32.f32 %0,%1;" : "=r"(u) : "f"(v)); return u;
}
static __device__ __forceinline__ float rnaf(float v) { return __uint_as_float(rna(v)); }
static __device__ __forceinline__ unsigned fau(float v) { return __float_as_uint(v); }

static __device__ __forceinline__ void mma8(float* d, const unsigned* a, unsigned b0, unsigned b1) {
    asm volatile("mma.sync.aligned.m16n8k8.row.col.f32.tf32.tf32.f32 "
                 "{%0,%1,%2,%3},{%4,%5,%6,%7},{%8,%9},{%0,%1,%2,%3};"
                 : "+f"(d[0]), "+f"(d[1]), "+f"(d[2]), "+f"(d[3])
                 : "r"(a[0]), "r"(a[1]), "r"(a[2]), "r"(a[3]), "r"(b0), "r"(b1));
}

// ---------------------------------------------------------------------------
__global__ void prep(const float* __restrict__ et, const int* __restrict__ at,
                     const float* __restrict__ wn, const float* __restrict__ wu)
{
    int k = blockIdx.x, l = blockIdx.y, e = threadIdx.x;
    float v;
    if (k < 384) {
        v = wu[((size_t)l * 512 + k) * 128 + e];
    } else {
        int k2 = k - 384, n = k2 >> 3, f = k2 & 7;
        const float* y  = et + at[n] * 128;
        const float* wf = wn + (l * 8 + f) * 128;
        const float* w3 = wu + ((size_t)l * 512 + 384) * 128;
        float a = 0.f;
        #pragma unroll 4
        for (int d = 0; d < 128; d++) a = fmaf(wf[d] * y[d], w3[(size_t)d * 128 + e], a);
        v = a;
    }
    int src = k >> 7, kr = k & 127, ks = kr >> 3, kt = kr & 7, t = kt & 3, cf = kt >> 2;
    int nq = e >> 5, ntp = (e >> 4) & 1, eh = (e >> 3) & 1, g = e & 7;
    int quad = ((((src * 16 + ks) * 4 + t) * 2 + ntp) * 4 + nq) * 8 + g;
    g_W2Q[l][quad * 4 + cf + 2 * eh] = rnaf(v);
}

// ---------------------------------------------------------------------------
__global__ void __launch_bounds__(NT) gnn(
    const float* __restrict__ r, const float* __restrict__ Rn,
    const float* __restrict__ ws, const float* __restrict__ wa,
    const float* __restrict__ bu, float* __restrict__ out)
{
    extern __shared__ __align__(16) float sm[];
    const int b = blockIdx.x, tid = threadIdx.x, w = tid >> 5, ln = tid & 31;
    const int g = ln >> 2, t = ln & 3;
    // GEMM2 / epilogue mapping
    const int half = w & 1;
    const int rt2 = w >> 3, nq = (w >> 1) & 3, ibase = rt2 * 16 + g;
    // GEMM1 mapping
    const int qp = w & 1, wm = (w >> 1) & 1, wd = w >> 2;
    const float DEL = 4.0f / 7.0f;
    float S[7];
    #pragma unroll
    for (int k = 0; k < 7; k++) S[k] = expf(-DEL * DEL * (float)(2 * k + 1));

    if (tid < 192) { int i = tid / 3, c = tid % 3; sm[O_R + i * 4 + c] = r[((size_t)b * 64 + i) * 3 + c]; }
    // stage we for all 3 layers once
    for (int p = tid; p < 6144; p += NT) {
        int l = p / 2048, rr = p - l * 2048;
        sm[O_WE3 + p] = (rr < 1024) ? ws[l * 1024 + rr] : wa[l * 1024 + rr - 1024];
    }
    __syncthreads();

    // ---- x0: raw staging (ZSQ) + XQ/X0Q frags + XTB ----
    for (int p = tid; p < 1024; p += NT) {
        int i = p >> 4, n = p & 15;
        float dx = sm[O_R + i * 4]     - Rn[((size_t)b * 16 + n) * 3];
        float dy = sm[O_R + i * 4 + 1] - Rn[((size_t)b * 16 + n) * 3 + 1];
        float dz = sm[O_R + i * 4 + 2] - Rn[((size_t)b * 16 + n) * 3 + 2];
        float d2 = fmaf(dx, dx, fmaf(dy, dy, dz * dz)) + 1e-12f;
        float ft = __expf(-d2), q = __expf(2.f * DEL * sqrtf(d2));
        int i16 = i >> 4, jl = i & 31;
        #pragma unroll
        for (int f = 0; f < 8; f++) {
            int k = n * 8 + f;
            sm[O_ZSQ + i * 128 + k] = ft;               // raw staging
            float fv = rnaf(ft);
            int fi = ((i16 * 64 + n * 4 + (f & 3)) * 8 + (i & 7)) * 4
                   + ((i >> 3) & 1) + 2 * ((f >> 2) & 1);
            sm[O_XQ + fi]  = fv;
            sm[O_X0Q + fi] = fv;
            int xb = ((((k >> 3) * 2 + (i >> 5)) * 4 + (jl >> 3)) * 8 + (k & 7)) * 4 + (jl & 3);
            sm[O_XTB + xb * 2 + ((jl >> 2) & 1)] = fv;
            if (f < 7) ft = ft * q * S[f];
        }
    }
    // ---- ee features -> global fragment quads (coalesced consumer order) ----
    for (int p = tid; p < 4096; p += NT) {
        int i = p >> 6, j = p & 63;
        float dx = sm[O_R + i * 4]     - sm[O_R + j * 4];
        float dy = sm[O_R + i * 4 + 1] - sm[O_R + j * 4 + 1];
        float dz = sm[O_R + i * 4 + 2] - sm[O_R + j * 4 + 2];
        float d2 = fmaf(dx, dx, fmaf(dy, dy, dz * dz)) + 1e-12f;
        float ft = (i == j) ? 0.f : __expf(-d2);
        float q = __expf(2.f * DEL * sqrtf(d2));
        int qd = (i >> 5) * 2 + (j >> 5), il = i & 31, jl = j & 31;
        int wm2 = il >> 4, g2 = il & 7, h = (il >> 3) & 1;
        int ks = jl >> 3, t2 = (jl & 7) & 3, c = (jl & 7) >> 2;
        float* gb = g_fq[b];
        #pragma unroll
        for (int f = 0; f < 8; f++) {
            int fi = (((((qd * 8 + f) * 2 + wm2) * 4 + ks) * 8 + g2) * 4 + t2) * 4 + h + 2 * c;
            gb[fi] = rnaf(ft);
            if (f < 7) ft = ft * q * S[f];
        }
    }
    __syncthreads();

    // ---- raw x residual into registers ----
    float xf[8];
    {
        const float* st = sm + O_ZSQ;
        #pragma unroll
        for (int ntl = 0; ntl < 2; ntl++) {
            int e = nq * 32 + (2 * half + ntl) * 8 + 2 * t;
            xf[ntl * 4 + 0] = st[ibase * 128 + e];
            xf[ntl * 4 + 1] = st[ibase * 128 + e + 1];
            xf[ntl * 4 + 2] = st[(ibase + 8) * 128 + e];
            xf[ntl * 4 + 3] = st[(ibase + 8) * 128 + e + 1];
        }
    }
    __syncthreads();   // staging reads done before GEMM1 overwrites ZSQ

    const float4* sm4 = (const float4*)sm;

    for (int l = 0; l < 3; l++) {
        // ===== GEMM1: 2 quadrants per warp (shared B frags, contiguous LDS) =====
        {
            const int jblk = qp;
            float2 Bf[4][2];
            #pragma unroll
            for (int ks = 0; ks < 4; ks++)
                #pragma unroll
                for (int nt = 0; nt < 2; nt++)
                    Bf[ks][nt] = *(const float2*)&sm[O_XTB +
                        ((((((wd * 2 + nt) * 2 + jblk) * 4 + ks) * 8 + g) * 4 + t)) * 2];

            const float4* gfq4 = (const float4*)g_fq[b];
            #pragma unroll 1
            for (int qi = 0; qi < 2; qi++) {
                const int iblk = qi, q = iblk * 2 + jblk, same = (iblk == jblk);
                float z[2][4] = {{0,0,0,0},{0,0,0,0}};
                const int weo = O_WE3 + l * 2048 + (same ? 0 : 1024);

                #pragma unroll 2
                for (int f = 0; f < 8; f++) {
                    float2 wv0 = *(const float2*)&sm[weo + f * 128 + wd * 16 + 2 * t];
                    float2 wv1 = *(const float2*)&sm[weo + f * 128 + wd * 16 + 8 + 2 * t];
                    float tf0[4] = {0,0,0,0}, tf1[4] = {0,0,0,0};
                    #pragma unroll
                    for (int ks = 0; ks < 4; ks++) {
                        float4 av = gfq4[((((q * 8 + f) * 2 + wm) * 4 + ks) * 8 + g) * 4 + t];
                        unsigned a[4] = {fau(av.x), fau(av.y), fau(av.z), fau(av.w)};
                        mma8(tf0, a, fau(Bf[ks][0].x), fau(Bf[ks][0].y));
                        mma8(tf1, a, fau(Bf[ks][1].x), fau(Bf[ks][1].y));
                    }
                    z[0][0] = fmaf(wv0.x, tf0[0], z[0][0]);
                    z[0][1] = fmaf(wv0.y, tf0[1], z[0][1]);
                    z[0][2] = fmaf(wv0.x, tf0[2], z[0][2]);
                    z[0][3] = fmaf(wv0.y, tf0[3], z[0][3]);
                    z[1][0] = fmaf(wv1.x, tf1[0], z[1][0]);
                    z[1][1] = fmaf(wv1.y, tf1[1], z[1][1]);
                    z[1][2] = fmaf(wv1.x, tf1[2], z[1][2]);
                    z[1][3] = fmaf(wv1.y, tf1[3], z[1][3]);
                }
                const int zo = (same ? O_ZSQ : O_ZAQ);
                const int i16 = iblk * 2 + wm;
                #pragma unroll
                for (int nt = 0; nt < 2; nt++)
                    #pragma unroll
                    for (int k01 = 0; k01 < 2; k01++) {
                        int d = wd * 16 + nt * 8 + 2 * t + k01;
                        int kf = (d >> 3) * 4 + (d & 3);
                        *(float2*)&sm[zo + ((i16 * 64 + kf) * 8 + g) * 4 + 2 * ((d >> 2) & 1)]
                            = make_float2(rnaf(z[nt][k01]), rnaf(z[nt][k01 + 2]));
                    }
            }
        }
        __syncthreads();

        // ===== GEMM2: contiguous A-frag LDS.128 + coalesced B LDG.128 =====
        float acc2[2][4];
        #pragma unroll
        for (int nt = 0; nt < 2; nt++)
            #pragma unroll
            for (int c = 0; c < 4; c++) acc2[nt][c] = 0.f;

        #pragma unroll 1
        for (int src = 0; src < 4; src++) {
            const int ap4 = ((src == 0) ? O_XQ : (src == 1) ? O_ZSQ : (src == 2) ? O_ZAQ : O_X0Q) >> 2;
            const float4* w2q4 = (const float4*)g_W2Q[l] + src * 4096;
            #pragma unroll 4
            for (int ks = 0; ks < 16; ks++) {
                float4 aq = sm4[ap4 + (rt2 * 64 + ks * 4 + t) * 8 + g];
                unsigned a[4] = {fau(aq.x), fau(aq.y), fau(aq.z), fau(aq.w)};
                float4 bv = w2q4[(((ks * 4 + t) * 2 + half) * 4 + nq) * 8 + g];
                mma8(acc2[0], a, fau(bv.x), fau(bv.y));
                mma8(acc2[1], a, fau(bv.z), fau(bv.w));
            }
        }
        __syncthreads();

        // ===== epilogue =====
        #pragma unroll
        for (int ntl = 0; ntl < 2; ntl++) {
            int nt = 2 * half + ntl;
            int e = nq * 32 + nt * 8 + 2 * t;
            float b0v = bu[l * 128 + e], b1v = bu[l * 128 + e + 1];
            float n00 = xf[ntl * 4 + 0] + tanhf(acc2[ntl][0] + b0v);
            float n01 = xf[ntl * 4 + 1] + tanhf(acc2[ntl][1] + b1v);
            float n10 = xf[ntl * 4 + 2] + tanhf(acc2[ntl][2] + b0v);
            float n11 = xf[ntl * 4 + 3] + tanhf(acc2[ntl][3] + b1v);
            xf[ntl * 4 + 0] = n00; xf[ntl * 4 + 1] = n01;
            xf[ntl * 4 + 2] = n10; xf[ntl * 4 + 3] = n11;
            if (l < 2) {
                #pragma unroll
                for (int k01 = 0; k01 < 2; k01++) {
                    int ee = e + k01;
                    float vlo = rnaf(k01 ? n01 : n00), vhi = rnaf(k01 ? n11 : n10);
                    int kf = (ee >> 3) * 4 + (ee & 3);
                    *(float2*)&sm[O_XQ + ((rt2 * 64 + kf) * 8 + g) * 4 + 2 * ((ee >> 2) & 1)]
                        = make_float2(vlo, vhi);
                    int jl = (rt2 & 1) * 16 + g;
                    int bse = ((((ee >> 3) * 2 + (rt2 >> 1)) * 4 + (jl >> 3)) * 8 + (ee & 7)) * 4 + (jl & 3);
                    sm[O_XTB + bse * 2 + ((jl >> 2) & 1)] = vlo;
                    int jl2 = jl + 8;
                    int bse2 = ((((ee >> 3) * 2 + (rt2 >> 1)) * 4 + (jl2 >> 3)) * 8 + (ee & 7)) * 4 + (jl2 & 3);
                    sm[O_XTB + bse2 * 2 + ((jl2 >> 2) & 1)] = vhi;
                }
            } else {
                out[((size_t)b * 64 + ibase) * 128 + e]         = n00;
                out[((size_t)b * 64 + ibase) * 128 + e + 1]     = n01;
                out[((size_t)b * 64 + ibase + 8) * 128 + e]     = n10;
                out[((size_t)b * 64 + ibase + 8) * 128 + e + 1] = n11;
            }
        }
        __syncthreads();
    }
}

extern "C" void kernel_launch(void* const* d_in, const int* in_sizes, int n_in,
                              void* d_out, int out_size)
{
    const float* r  = (const float*)d_in[0];
    const float* Rn = (const float*)d_in[1];
    const float* et = (const float*)d_in[2];
    const float* ws = (const float*)d_in[3];
    const float* wa = (const float*)d_in[4];
    const float* wn = (const float*)d_in[5];
    const float* wu = (const float*)d_in[6];
    const float* bu = (const float*)d_in[7];
    const int*   at = (const int*)d_in[8];
    float* out = (float*)d_out;

    const int smem = SMF * (int)sizeof(float);   // 189,440 B
    cudaFuncSetAttribute(gnn, cudaFuncAttributeMaxDynamicSharedMemorySize, smem);
    prep<<<dim3(512, 3), 128>>>(et, at, wn, wu);
    gnn<<<512, NT, smem>>>(r, Rn, ws, wa, bu, out);
}

// round 13
// speedup vs baseline: 1.3965x; 1.3965x over previous
#include <cuda_runtime.h>
#include <math.h>
#include <stdint.h>

#define NT 1024
// ---- smem float offsets ----
// quad panels (stride 68 f4, proven conflict-free for LDS.128):
//   f4 idx = (i16*8+g)*68 + kf,  kf=(k>>3)*4+(k&3), comp = ((i>>3)&1) + 2*((k>>2)&1)
#define O_XQ  0        // x     8704 floats
#define O_X0Q 8704     // x0    8704
#define O_ZSQ 17408    // z_s   8704 (also raw-x0 staging [i*128+k])
#define O_ZAQ 26112    // z_a   8704
#define O_XTP 34816    // x^T [128 d-rows][36 f2]  9216 floats (stride 36: bank-clean)
#define O_WE  44032    // we_same[8][128] + we_anti[8][128]  2048
#define O_R   46080    // positions [64][4]
#define SMF   46336    // 185,344 B

__device__ float g_fq[512][32768];    // feat frag-quads
__device__ float g_W2Q[3][65536];     // W2 frag-quads

static __device__ __forceinline__ unsigned rna(float v) {
    unsigned u; asm("cvt.rna.tf32.f32 %0,%1;" : "=r"(u) : "f"(v)); return u;
}
static __device__ __forceinline__ float rnaf(float v) { return __uint_as_float(rna(v)); }
static __device__ __forceinline__ unsigned fau(float v) { return __float_as_uint(v); }

static __device__ __forceinline__ void mma8(float* d, const unsigned* a, unsigned b0, unsigned b1) {
    asm volatile("mma.sync.aligned.m16n8k8.row.col.f32.tf32.tf32.f32 "
                 "{%0,%1,%2,%3},{%4,%5,%6,%7},{%8,%9},{%0,%1,%2,%3};"
                 : "+f"(d[0]), "+f"(d[1]), "+f"(d[2]), "+f"(d[3])
                 : "r"(a[0]), "r"(a[1]), "r"(a[2]), "r"(a[3]), "r"(b0), "r"(b1));
}

// ---------------------------------------------------------------------------
__global__ void prep(const float* __restrict__ et, const int* __restrict__ at,
                     const float* __restrict__ wn, const float* __restrict__ wu)
{
    int k = blockIdx.x, l = blockIdx.y, e = threadIdx.x;
    float v;
    if (k < 384) {
        v = wu[((size_t)l * 512 + k) * 128 + e];
    } else {
        int k2 = k - 384, n = k2 >> 3, f = k2 & 7;
        const float* y  = et + at[n] * 128;
        const float* wf = wn + (l * 8 + f) * 128;
        const float* w3 = wu + ((size_t)l * 512 + 384) * 128;
        float a = 0.f;
        #pragma unroll 4
        for (int d = 0; d < 128; d++) a = fmaf(wf[d] * y[d], w3[(size_t)d * 128 + e], a);
        v = a;
    }
    int src = k >> 7, kr = k & 127, ks = kr >> 3, kt = kr & 7, t = kt & 3, cf = kt >> 2;
    int nq = e >> 5, ntp = (e >> 4) & 1, eh = (e >> 3) & 1, g = e & 7;
    int quad = ((((src * 16 + ks) * 4 + t) * 2 + ntp) * 4 + nq) * 8 + g;
    g_W2Q[l][quad * 4 + cf + 2 * eh] = rnaf(v);
}

// ---------------------------------------------------------------------------
__global__ void __launch_bounds__(NT) gnn(
    const float* __restrict__ r, const float* __restrict__ Rn,
    const float* __restrict__ ws, const float* __restrict__ wa,
    const float* __restrict__ bu, float* __restrict__ out)
{
    extern __shared__ __align__(16) float sm[];
    const int b = blockIdx.x, tid = threadIdx.x, w = tid >> 5, ln = tid & 31;
    const int g = ln >> 2, t = ln & 3;
    // GEMM2 / epilogue mapping
    const int half = w & 1;
    const int rt2 = w >> 3, nq = (w >> 1) & 3, ibase = rt2 * 16 + g;
    // GEMM1 mapping
    const int qp = w & 1, wm = (w >> 1) & 1, wd = w >> 2;
    const float DEL = 4.0f / 7.0f;
    float S[7];
    #pragma unroll
    for (int k = 0; k < 7; k++) S[k] = expf(-DEL * DEL * (float)(2 * k + 1));

    if (tid < 192) { int i = tid / 3, c = tid % 3; sm[O_R + i * 4 + c] = r[((size_t)b * 64 + i) * 3 + c]; }
    __syncthreads();

    // ---- x0: raw staging (ZSQ) + XQ/X0Q quads + XTP (one task per thread) ----
    {
        int p = tid;   // 1024 tasks
        int i = p >> 4, n = p & 15;
        float dx = sm[O_R + i * 4]     - Rn[((size_t)b * 16 + n) * 3];
        float dy = sm[O_R + i * 4 + 1] - Rn[((size_t)b * 16 + n) * 3 + 1];
        float dz = sm[O_R + i * 4 + 2] - Rn[((size_t)b * 16 + n) * 3 + 2];
        float d2 = fmaf(dx, dx, fmaf(dy, dy, dz * dz)) + 1e-12f;
        float ft = __expf(-d2), q = __expf(2.f * DEL * sqrtf(d2));
        int i16 = i >> 4, g2 = i & 7, h = (i >> 3) & 1;
        int pi = (i >> 3) * 4 + (i & 3), ci = (i >> 2) & 1;
        #pragma unroll
        for (int f = 0; f < 8; f++) {
            int k = n * 8 + f;
            sm[O_ZSQ + i * 128 + k] = ft;               // raw staging
            float fv = rnaf(ft);
            int fi = ((i16 * 8 + g2) * 68 + n * 4 + (f & 3)) * 4 + h + 2 * (f >> 2);
            sm[O_XQ + fi]  = fv;
            sm[O_X0Q + fi] = fv;
            sm[O_XTP + (k * 36 + pi) * 2 + ci] = fv;
            if (f < 7) ft = ft * q * S[f];
        }
    }
    // ---- ee features: one g_fq float4 column per thread (coalesced STG.128) ----
    {
        int w5 = w;                                     // 0..31
        int qd = w5 >> 3, wm2 = (w5 >> 2) & 1, ks = w5 & 3;
        int iblk = qd >> 1, jblk = qd & 1;
        int i0a = iblk * 32 + wm2 * 16 + g;
        int j0a = jblk * 32 + ks * 8 + t;
        float ftv[4], qqv[4];
        #pragma unroll
        for (int a = 0; a < 2; a++)
            #pragma unroll
            for (int c = 0; c < 2; c++) {
                int ii = i0a + a * 8, jj = j0a + c * 4;
                float dx = sm[O_R + ii * 4]     - sm[O_R + jj * 4];
                float dy = sm[O_R + ii * 4 + 1] - sm[O_R + jj * 4 + 1];
                float dz = sm[O_R + ii * 4 + 2] - sm[O_R + jj * 4 + 2];
                float d2 = fmaf(dx, dx, fmaf(dy, dy, dz * dz)) + 1e-12f;
                int idx = a + 2 * c;
                ftv[idx] = (ii == jj) ? 0.f : __expf(-d2);
                qqv[idx] = __expf(2.f * DEL * sqrtf(d2));
            }
        float4* gb4 = (float4*)g_fq[b];
        #pragma unroll
        for (int f = 0; f < 8; f++) {
            gb4[((((qd * 8 + f) * 2 + wm2) * 4 + ks) * 8 + g) * 4 + t] =
                make_float4(rnaf(ftv[0]), rnaf(ftv[1]), rnaf(ftv[2]), rnaf(ftv[3]));
            if (f < 7) {
                #pragma unroll
                for (int u = 0; u < 4; u++) ftv[u] = ftv[u] * qqv[u] * S[f];
            }
        }
    }
    __syncthreads();

    // ---- raw x residual into registers ----
    float xf[8];
    {
        const float* st = sm + O_ZSQ;
        #pragma unroll
        for (int ntl = 0; ntl < 2; ntl++) {
            int e = nq * 32 + (2 * half + ntl) * 8 + 2 * t;
            xf[ntl * 4 + 0] = st[ibase * 128 + e];
            xf[ntl * 4 + 1] = st[ibase * 128 + e + 1];
            xf[ntl * 4 + 2] = st[(ibase + 8) * 128 + e];
            xf[ntl * 4 + 3] = st[(ibase + 8) * 128 + e + 1];
        }
    }
    __syncthreads();   // staging reads done before GEMM1 overwrites ZSQ

    const float4* sm4 = (const float4*)sm;

    for (int l = 0; l < 3; l++) {
        for (int p = tid; p < 2048; p += NT)
            sm[O_WE + p] = (p < 1024) ? ws[l * 1024 + p] : wa[l * 1024 + p - 1024];
        __syncthreads();

        // ===== GEMM1: 2 quadrants per warp (shared B frags) =====
        {
            const int jblk = qp;
            float2 Bf[4][2];
            #pragma unroll
            for (int ks = 0; ks < 4; ks++)
                #pragma unroll
                for (int nt = 0; nt < 2; nt++)
                    Bf[ks][nt] = *(const float2*)&sm[O_XTP +
                        ((wd * 16 + nt * 8 + g) * 36 + jblk * 16 + ks * 4 + t) * 2];

            const float4* gfq4 = (const float4*)g_fq[b];
            #pragma unroll 1
            for (int qi = 0; qi < 2; qi++) {
                const int iblk = qi, q = iblk * 2 + jblk, same = (iblk == jblk);
                float z[2][4] = {{0,0,0,0},{0,0,0,0}};
                const int weo = O_WE + (same ? 0 : 1024);

                #pragma unroll 2
                for (int f = 0; f < 8; f++) {
                    float2 wv0 = *(const float2*)&sm[weo + f * 128 + wd * 16 + 2 * t];
                    float2 wv1 = *(const float2*)&sm[weo + f * 128 + wd * 16 + 8 + 2 * t];
                    float tf0[4] = {0,0,0,0}, tf1[4] = {0,0,0,0};
                    #pragma unroll
                    for (int ks = 0; ks < 4; ks++) {
                        float4 av = gfq4[((((q * 8 + f) * 2 + wm) * 4 + ks) * 8 + g) * 4 + t];
                        unsigned a[4] = {fau(av.x), fau(av.y), fau(av.z), fau(av.w)};
                        mma8(tf0, a, fau(Bf[ks][0].x), fau(Bf[ks][0].y));
                        mma8(tf1, a, fau(Bf[ks][1].x), fau(Bf[ks][1].y));
                    }
                    z[0][0] = fmaf(wv0.x, tf0[0], z[0][0]);
                    z[0][1] = fmaf(wv0.y, tf0[1], z[0][1]);
                    z[0][2] = fmaf(wv0.x, tf0[2], z[0][2]);
                    z[0][3] = fmaf(wv0.y, tf0[3], z[0][3]);
                    z[1][0] = fmaf(wv1.x, tf1[0], z[1][0]);
                    z[1][1] = fmaf(wv1.y, tf1[1], z[1][1]);
                    z[1][2] = fmaf(wv1.x, tf1[2], z[1][2]);
                    z[1][3] = fmaf(wv1.y, tf1[3], z[1][3]);
                }
                const int zo = (same ? O_ZSQ : O_ZAQ);
                #pragma unroll
                for (int nt = 0; nt < 2; nt++)
                    #pragma unroll
                    for (int k01 = 0; k01 < 2; k01++) {
                        int kt = 2 * t + k01;
                        int base = zo + (((iblk * 2 + wm) * 8 + g) * 68
                                   + (wd * 2 + nt) * 4 + (kt & 3)) * 4 + 2 * (kt >> 2);
                        *(float2*)&sm[base] =
                            make_float2(rnaf(z[nt][k01]), rnaf(z[nt][k01 + 2]));
                    }
            }
        }
        __syncthreads();

        // ===== GEMM2 (unchanged from R11) =====
        float acc2[2][4];
        #pragma unroll
        for (int nt = 0; nt < 2; nt++)
            #pragma unroll
            for (int c = 0; c < 4; c++) acc2[nt][c] = 0.f;

        #pragma unroll 1
        for (int src = 0; src < 4; src++) {
            const int ap4 = ((src == 0) ? O_XQ : (src == 1) ? O_ZSQ : (src == 2) ? O_ZAQ : O_X0Q) >> 2;
            const float4* w2q4 = (const float4*)g_W2Q[l] + src * 4096;
            #pragma unroll 4
            for (int ks = 0; ks < 16; ks++) {
                float4 aq = sm4[ap4 + (rt2 * 8 + g) * 68 + ks * 4 + t];
                unsigned a[4] = {fau(aq.x), fau(aq.y), fau(aq.z), fau(aq.w)};
                float4 bv = w2q4[(((ks * 4 + t) * 2 + half) * 4 + nq) * 8 + g];
                mma8(acc2[0], a, fau(bv.x), fau(bv.y));
                mma8(acc2[1], a, fau(bv.z), fau(bv.w));
            }
        }
        __syncthreads();

        // ===== epilogue =====
        const int pi0 = rt2 * 8 + (g & 3), pi1 = rt2 * 8 + 4 + (g & 3), cgi = (g >> 2) & 1;
        #pragma unroll
        for (int ntl = 0; ntl < 2; ntl++) {
            int nt = 2 * half + ntl;
            int e = nq * 32 + nt * 8 + 2 * t;
            float b0v = bu[l * 128 + e], b1v = bu[l * 128 + e + 1];
            float n00 = xf[ntl * 4 + 0] + tanhf(acc2[ntl][0] + b0v);
            float n01 = xf[ntl * 4 + 1] + tanhf(acc2[ntl][1] + b1v);
            float n10 = xf[ntl * 4 + 2] + tanhf(acc2[ntl][2] + b0v);
            float n11 = xf[ntl * 4 + 3] + tanhf(acc2[ntl][3] + b1v);
            xf[ntl * 4 + 0] = n00; xf[ntl * 4 + 1] = n01;
            xf[ntl * 4 + 2] = n10; xf[ntl * 4 + 3] = n11;
            if (l < 2) {
                int base = O_XQ + ((rt2 * 8 + g) * 68 + (nq * 4 + nt) * 4) * 4;
                int k0 = 2 * t, k1 = 2 * t + 1;
                *(float2*)&sm[base + (k0 & 3) * 4 + 2 * (k0 >> 2)] =
                    make_float2(rnaf(n00), rnaf(n10));
                *(float2*)&sm[base + (k1 & 3) * 4 + 2 * (k1 >> 2)] =
                    make_float2(rnaf(n01), rnaf(n11));
                sm[O_XTP + (e * 36 + pi0) * 2 + cgi]       = rnaf(n00);
                sm[O_XTP + ((e + 1) * 36 + pi0) * 2 + cgi] = rnaf(n01);
                sm[O_XTP + (e * 36 + pi1) * 2 + cgi]       = rnaf(n10);
                sm[O_XTP + ((e + 1) * 36 + pi1) * 2 + cgi] = rnaf(n11);
            } else {
                out[((size_t)b * 64 + ibase) * 128 + e]         = n00;
                out[((size_t)b * 64 + ibase) * 128 + e + 1]     = n01;
                out[((size_t)b * 64 + ibase + 8) * 128 + e]     = n10;
                out[((size_t)b * 64 + ibase + 8) * 128 + e + 1] = n11;
            }
        }
        __syncthreads();
    }
}

extern "C" void kernel_launch(void* const* d_in, const int* in_sizes, int n_in,
                              void* d_out, int out_size)
{
    const float* r  = (const float*)d_in[0];
    const float* Rn = (const float*)d_in[1];
    const float* et = (const float*)d_in[2];
    const float* ws = (const float*)d_in[3];
    const float* wa = (const float*)d_in[4];
    const float* wn = (const float*)d_in[5];
    const float* wu = (const float*)d_in[6];
    const float* bu = (const float*)d_in[7];
    const int*   at = (const int*)d_in[8];
    float* out = (float*)d_out;

    const int smem = SMF * (int)sizeof(float);   // 185,344 B
    cudaFuncSetAttribute(gnn, cudaFuncAttributeMaxDynamicSharedMemorySize, smem);
    prep<<<dim3(512, 3), 128>>>(et, at, wn, wu);
    gnn<<<512, NT, smem>>>(r, Rn, ws, wa, bu, out);
}

// round 14
// speedup vs baseline: 1.5437x; 1.1054x over previous
#include <cuda_runtime.h>
#include <math.h>
#include <stdint.h>

#define NT 512
// ---- smem float offsets (identical layouts to R13) ----
#define O_XQ  0        // x     8704 floats (stride-68 f4 quad panel)
#define O_X0Q 8704     // x0    8704
#define O_ZSQ 17408    // z_s   8704 (also raw-x0 staging [i*128+k])
#define O_ZAQ 26112    // z_a   8704
#define O_XTP 34816    // x^T [128][36 f2]  9216
#define O_WE  44032    // we_same[8][128] + we_anti[8][128]  2048
#define O_R   46080    // positions [64][4]
#define SMF   46336    // 185,344 B

__device__ float g_fq[512][32768];    // feat frag-quads
__device__ float g_W2Q[3][65536];     // W2 frag-quads

static __device__ __forceinline__ unsigned rna(float v) {
    unsigned u; asm("cvt.rna.tf32.f32 %0,%1;" : "=r"(u) : "f"(v)); return u;
}
static __device__ __forceinline__ float rnaf(float v) { return __uint_as_float(rna(v)); }
static __device__ __forceinline__ unsigned fau(float v) { return __float_as_uint(v); }

static __device__ __forceinline__ void mma8(float* d, const unsigned* a, unsigned b0, unsigned b1) {
    asm volatile("mma.sync.aligned.m16n8k8.row.col.f32.tf32.tf32.f32 "
                 "{%0,%1,%2,%3},{%4,%5,%6,%7},{%8,%9},{%0,%1,%2,%3};"
                 : "+f"(d[0]), "+f"(d[1]), "+f"(d[2]), "+f"(d[3])
                 : "r"(a[0]), "r"(a[1]), "r"(a[2]), "r"(a[3]), "r"(b0), "r"(b1));
}

// ---------------------------------------------------------------------------
__global__ void prep(const float* __restrict__ et, const int* __restrict__ at,
                     const float* __restrict__ wn, const float* __restrict__ wu)
{
    int k = blockIdx.x, l = blockIdx.y, e = threadIdx.x;
    float v;
    if (k < 384) {
        v = wu[((size_t)l * 512 + k) * 128 + e];
    } else {
        int k2 = k - 384, n = k2 >> 3, f = k2 & 7;
        const float* y  = et + at[n] * 128;
        const float* wf = wn + (l * 8 + f) * 128;
        const float* w3 = wu + ((size_t)l * 512 + 384) * 128;
        float a = 0.f;
        #pragma unroll 4
        for (int d = 0; d < 128; d++) a = fmaf(wf[d] * y[d], w3[(size_t)d * 128 + e], a);
        v = a;
    }
    int src = k >> 7, kr = k & 127, ks = kr >> 3, kt = kr & 7, t = kt & 3, cf = kt >> 2;
    int nq = e >> 5, ntp = (e >> 4) & 1, eh = (e >> 3) & 1, g = e & 7;
    int quad = ((((src * 16 + ks) * 4 + t) * 2 + ntp) * 4 + nq) * 8 + g;
    g_W2Q[l][quad * 4 + cf + 2 * eh] = rnaf(v);
}

// ---------------------------------------------------------------------------
__global__ void __launch_bounds__(NT) gnn(
    const float* __restrict__ r, const float* __restrict__ Rn,
    const float* __restrict__ ws, const float* __restrict__ wa,
    const float* __restrict__ bu, float* __restrict__ out)
{
    extern __shared__ __align__(16) float sm[];
    const int b = blockIdx.x, tid = threadIdx.x, w = tid >> 5, ln = tid & 31;
    const int g = ln >> 2, t = ln & 3;
    // GEMM2 / epilogue mapping: 16 warps = (rt2, nq), each N=32
    const int rt2 = w >> 2, nq = w & 3, ibase = rt2 * 16 + g;
    // GEMM1 mapping: 16 warps = (jblk, wm, wd2), each d-width 32
    const int jblk = w & 1, wm = (w >> 1) & 1, wd2 = w >> 2;
    const float DEL = 4.0f / 7.0f;
    float S[7];
    #pragma unroll
    for (int k = 0; k < 7; k++) S[k] = expf(-DEL * DEL * (float)(2 * k + 1));

    if (tid < 192) { int i = tid / 3, c = tid % 3; sm[O_R + i * 4 + c] = r[((size_t)b * 64 + i) * 3 + c]; }
    __syncthreads();

    // ---- x0: raw staging (ZSQ) + XQ/X0Q quads + XTP ----
    for (int p = tid; p < 1024; p += NT) {
        int i = p >> 4, n = p & 15;
        float dx = sm[O_R + i * 4]     - Rn[((size_t)b * 16 + n) * 3];
        float dy = sm[O_R + i * 4 + 1] - Rn[((size_t)b * 16 + n) * 3 + 1];
        float dz = sm[O_R + i * 4 + 2] - Rn[((size_t)b * 16 + n) * 3 + 2];
        float d2 = fmaf(dx, dx, fmaf(dy, dy, dz * dz)) + 1e-12f;
        float ft = __expf(-d2), q = __expf(2.f * DEL * sqrtf(d2));
        int i16 = i >> 4, g2 = i & 7, h = (i >> 3) & 1;
        int pi = (i >> 3) * 4 + (i & 3), ci = (i >> 2) & 1;
        #pragma unroll
        for (int f = 0; f < 8; f++) {
            int k = n * 8 + f;
            sm[O_ZSQ + i * 128 + k] = ft;               // raw staging
            float fv = rnaf(ft);
            int fi = ((i16 * 8 + g2) * 68 + n * 4 + (f & 3)) * 4 + h + 2 * (f >> 2);
            sm[O_XQ + fi]  = fv;
            sm[O_X0Q + fi] = fv;
            sm[O_XTP + (k * 36 + pi) * 2 + ci] = fv;
            if (f < 7) ft = ft * q * S[f];
        }
    }
    // ---- ee features: 32 column-tasks over 16 warps (2 per warp) ----
    #pragma unroll 1
    for (int w5 = w; w5 < 32; w5 += 16) {
        int qd = w5 >> 3, wm2 = (w5 >> 2) & 1, ks = w5 & 3;
        int iblk = qd >> 1, jb = qd & 1;
        int i0a = iblk * 32 + wm2 * 16 + g;
        int j0a = jb * 32 + ks * 8 + t;
        float ftv[4], qqv[4];
        #pragma unroll
        for (int a = 0; a < 2; a++)
            #pragma unroll
            for (int c = 0; c < 2; c++) {
                int ii = i0a + a * 8, jj = j0a + c * 4;
                float dx = sm[O_R + ii * 4]     - sm[O_R + jj * 4];
                float dy = sm[O_R + ii * 4 + 1] - sm[O_R + jj * 4 + 1];
                float dz = sm[O_R + ii * 4 + 2] - sm[O_R + jj * 4 + 2];
                float d2 = fmaf(dx, dx, fmaf(dy, dy, dz * dz)) + 1e-12f;
                int idx = a + 2 * c;
                ftv[idx] = (ii == jj) ? 0.f : __expf(-d2);
                qqv[idx] = __expf(2.f * DEL * sqrtf(d2));
            }
        float4* gb4 = (float4*)g_fq[b];
        #pragma unroll
        for (int f = 0; f < 8; f++) {
            gb4[((((qd * 8 + f) * 2 + wm2) * 4 + ks) * 8 + g) * 4 + t] =
                make_float4(rnaf(ftv[0]), rnaf(ftv[1]), rnaf(ftv[2]), rnaf(ftv[3]));
            if (f < 7) {
                #pragma unroll
                for (int u = 0; u < 4; u++) ftv[u] = ftv[u] * qqv[u] * S[f];
            }
        }
    }
    __syncthreads();

    // ---- raw x residual into registers (16 outputs per thread) ----
    float xf[16];
    {
        const float* st = sm + O_ZSQ;
        #pragma unroll
        for (int nt = 0; nt < 4; nt++) {
            int e = nq * 32 + nt * 8 + 2 * t;
            xf[nt * 4 + 0] = st[ibase * 128 + e];
            xf[nt * 4 + 1] = st[ibase * 128 + e + 1];
            xf[nt * 4 + 2] = st[(ibase + 8) * 128 + e];
            xf[nt * 4 + 3] = st[(ibase + 8) * 128 + e + 1];
        }
    }
    __syncthreads();   // staging reads done before GEMM1 overwrites ZSQ

    const float4* sm4 = (const float4*)sm;

    for (int l = 0; l < 3; l++) {
        for (int p = tid; p < 2048; p += NT)
            sm[O_WE + p] = (p < 1024) ? ws[l * 1024 + p] : wa[l * 1024 + p - 1024];
        __syncthreads();

        // ===== GEMM1: warp covers d-width 32 (4 n8-tiles), both iblk quadrants =====
        {
            float2 Bf[4][4];
            #pragma unroll
            for (int ks = 0; ks < 4; ks++)
                #pragma unroll
                for (int nt = 0; nt < 4; nt++)
                    Bf[ks][nt] = *(const float2*)&sm[O_XTP +
                        ((wd2 * 32 + nt * 8 + g) * 36 + jblk * 16 + ks * 4 + t) * 2];

            const float4* gfq4 = (const float4*)g_fq[b];
            #pragma unroll 1
            for (int qi = 0; qi < 2; qi++) {
                const int iblk = qi, q = iblk * 2 + jblk, same = (iblk == jblk);
                float z[4][4];
                #pragma unroll
                for (int nt = 0; nt < 4; nt++)
                    #pragma unroll
                    for (int c = 0; c < 4; c++) z[nt][c] = 0.f;
                const int weo = O_WE + (same ? 0 : 1024);

                #pragma unroll 2
                for (int f = 0; f < 8; f++) {
                    float2 wv[4];
                    #pragma unroll
                    for (int nt = 0; nt < 4; nt++)
                        wv[nt] = *(const float2*)&sm[weo + f * 128 + wd2 * 32 + nt * 8 + 2 * t];
                    float tf[4][4];
                    #pragma unroll
                    for (int nt = 0; nt < 4; nt++)
                        #pragma unroll
                        for (int c = 0; c < 4; c++) tf[nt][c] = 0.f;
                    #pragma unroll
                    for (int ks = 0; ks < 4; ks++) {
                        float4 av = gfq4[((((q * 8 + f) * 2 + wm) * 4 + ks) * 8 + g) * 4 + t];
                        unsigned a[4] = {fau(av.x), fau(av.y), fau(av.z), fau(av.w)};
                        #pragma unroll
                        for (int nt = 0; nt < 4; nt++)
                            mma8(tf[nt], a, fau(Bf[ks][nt].x), fau(Bf[ks][nt].y));
                    }
                    #pragma unroll
                    for (int nt = 0; nt < 4; nt++) {
                        z[nt][0] = fmaf(wv[nt].x, tf[nt][0], z[nt][0]);
                        z[nt][1] = fmaf(wv[nt].y, tf[nt][1], z[nt][1]);
                        z[nt][2] = fmaf(wv[nt].x, tf[nt][2], z[nt][2]);
                        z[nt][3] = fmaf(wv[nt].y, tf[nt][3], z[nt][3]);
                    }
                }
                const int zo = (same ? O_ZSQ : O_ZAQ);
                const int i16 = iblk * 2 + wm;
                #pragma unroll
                for (int nt = 0; nt < 4; nt++)
                    #pragma unroll
                    for (int k01 = 0; k01 < 2; k01++) {
                        int kt = 2 * t + k01;
                        int base = zo + ((i16 * 8 + g) * 68
                                   + (wd2 * 4 + nt) * 4 + (kt & 3)) * 4 + 2 * (kt >> 2);
                        *(float2*)&sm[base] =
                            make_float2(rnaf(z[nt][k01]), rnaf(z[nt][k01 + 2]));
                    }
            }
        }
        __syncthreads();

        // ===== GEMM2: warp covers N=32 (2 B-quads), 4 independent mma chains =====
        float acc2[4][4];
        #pragma unroll
        for (int nt = 0; nt < 4; nt++)
            #pragma unroll
            for (int c = 0; c < 4; c++) acc2[nt][c] = 0.f;

        #pragma unroll 1
        for (int src = 0; src < 4; src++) {
            const int ap4 = ((src == 0) ? O_XQ : (src == 1) ? O_ZSQ : (src == 2) ? O_ZAQ : O_X0Q) >> 2;
            const float4* w2q4 = (const float4*)g_W2Q[l] + src * 4096;
            #pragma unroll 4
            for (int ks = 0; ks < 16; ks++) {
                float4 aq = sm4[ap4 + (rt2 * 8 + g) * 68 + ks * 4 + t];
                unsigned a[4] = {fau(aq.x), fau(aq.y), fau(aq.z), fau(aq.w)};
                float4 b0 = w2q4[(((ks * 4 + t) * 2 + 0) * 4 + nq) * 8 + g];
                float4 b1 = w2q4[(((ks * 4 + t) * 2 + 1) * 4 + nq) * 8 + g];
                mma8(acc2[0], a, fau(b0.x), fau(b0.y));
                mma8(acc2[1], a, fau(b0.z), fau(b0.w));
                mma8(acc2[2], a, fau(b1.x), fau(b1.y));
                mma8(acc2[3], a, fau(b1.z), fau(b1.w));
            }
        }
        __syncthreads();

        // ===== epilogue: 16 outputs per thread =====
        const int pi0 = rt2 * 8 + (g & 3), pi1 = rt2 * 8 + 4 + (g & 3), cgi = (g >> 2) & 1;
        #pragma unroll
        for (int nt = 0; nt < 4; nt++) {
            int e = nq * 32 + nt * 8 + 2 * t;
            float b0v = bu[l * 128 + e], b1v = bu[l * 128 + e + 1];
            float n00 = xf[nt * 4 + 0] + tanhf(acc2[nt][0] + b0v);
            float n01 = xf[nt * 4 + 1] + tanhf(acc2[nt][1] + b1v);
            float n10 = xf[nt * 4 + 2] + tanhf(acc2[nt][2] + b0v);
            float n11 = xf[nt * 4 + 3] + tanhf(acc2[nt][3] + b1v);
            xf[nt * 4 + 0] = n00; xf[nt * 4 + 1] = n01;
            xf[nt * 4 + 2] = n10; xf[nt * 4 + 3] = n11;
            if (l < 2) {
                int base = O_XQ + ((rt2 * 8 + g) * 68 + (nq * 4 + nt) * 4) * 4;
                int k0 = 2 * t, k1 = 2 * t + 1;
                *(float2*)&sm[base + (k0 & 3) * 4 + 2 * (k0 >> 2)] =
                    make_float2(rnaf(n00), rnaf(n10));
                *(float2*)&sm[base + (k1 & 3) * 4 + 2 * (k1 >> 2)] =
                    make_float2(rnaf(n01), rnaf(n11));
                sm[O_XTP + (e * 36 + pi0) * 2 + cgi]       = rnaf(n00);
                sm[O_XTP + ((e + 1) * 36 + pi0) * 2 + cgi] = rnaf(n01);
                sm[O_XTP + (e * 36 + pi1) * 2 + cgi]       = rnaf(n10);
                sm[O_XTP + ((e + 1) * 36 + pi1) * 2 + cgi] = rnaf(n11);
            } else {
                out[((size_t)b * 64 + ibase) * 128 + e]         = n00;
                out[((size_t)b * 64 + ibase) * 128 + e + 1]     = n01;
                out[((size_t)b * 64 + ibase + 8) * 128 + e]     = n10;
                out[((size_t)b * 64 + ibase + 8) * 128 + e + 1] = n11;
            }
        }
        __syncthreads();
    }
}

extern "C" void kernel_launch(void* const* d_in, const int* in_sizes, int n_in,
                              void* d_out, int out_size)
{
    const float* r  = (const float*)d_in[0];
    const float* Rn = (const float*)d_in[1];
    const float* et = (const float*)d_in[2];
    const float* ws = (const float*)d_in[3];
    const float* wa = (const float*)d_in[4];
    const float* wn = (const float*)d_in[5];
    const float* wu = (const float*)d_in[6];
    const float* bu = (const float*)d_in[7];
    const int*   at = (const int*)d_in[8];
    float* out = (float*)d_out;

    const int smem = SMF * (int)sizeof(float);   // 185,344 B
    cudaFuncSetAttribute(gnn, cudaFuncAttributeMaxDynamicSharedMemorySize, smem);
    prep<<<dim3(512, 3), 128>>>(et, at, wn, wu);
    gnn<<<512, NT, smem>>>(r, Rn, ws, wa, bu, out);
}

// round 15
// speedup vs baseline: 2.7430x; 1.7770x over previous
#include <cuda_runtime.h>
#include <cuda_fp16.h>
#include <math.h>
#include <stdint.h>

#define NT 512
// ---- smem float offsets ----
// fp16 quad panels (A-of-GEMM2 type): float4 idx = (i16*8+ks)*32 + g*4 + t
//   comps(half2): c0=(row g,k-lo) c1=(row g+8,k-lo) c2=(g,k-hi) c3=(g+8,k-hi); half lane = k&1
#define O_XQ  0        // x   4096 floats
#define O_X0Q 4096     // x0  4096
#define O_ZSQ 8192     // z_s 4096  (ZSQ..ZAQ doubles as raw-x0 staging [i*128+k])
#define O_ZAQ 12288    // z_a 4096
#define O_XT  16384    // x^T 4096: f4 idx=((jb*2+ksj)*8+dp)*32+g*4+t
#define O_WE  20480    // we_same[8][128]+we_anti[8][128] fp32  2048
#define O_R   22528    // positions [64][4]
#define SMF   22784    // 91,136 B

__device__ __half g_fqh[512][32768];   // feat fp16 quads [q][f][wm][ks][g][t]
__device__ __half g_W2h[3][65536];     // W2 fp16 quads [src][ks][t][np][nq][g]

static __device__ __forceinline__ unsigned h2u(float a, float b) {
    __half2 h = __floats2half2_rn(a, b);
    return *(unsigned*)&h;
}
static __device__ __forceinline__ void mma16(float* d, const unsigned* a, unsigned b0, unsigned b1) {
    asm volatile("mma.sync.aligned.m16n8k16.row.col.f32.f16.f16.f32 "
                 "{%0,%1,%2,%3},{%4,%5,%6,%7},{%8,%9},{%0,%1,%2,%3};"
                 : "+f"(d[0]), "+f"(d[1]), "+f"(d[2]), "+f"(d[3])
                 : "r"(a[0]), "r"(a[1]), "r"(a[2]), "r"(a[3]), "r"(b0), "r"(b1));
}

// ---------------------------------------------------------------------------
__global__ void prep(const float* __restrict__ et, const int* __restrict__ at,
                     const float* __restrict__ wn, const float* __restrict__ wu)
{
    int k = blockIdx.x, l = blockIdx.y, e = threadIdx.x;
    float v;
    if (k < 384) {
        v = wu[((size_t)l * 512 + k) * 128 + e];
    } else {
        int k2 = k - 384, n = k2 >> 3, f = k2 & 7;
        const float* y  = et + at[n] * 128;
        const float* wf = wn + (l * 8 + f) * 128;
        const float* w3 = wu + ((size_t)l * 512 + 384) * 128;
        float a = 0.f;
        #pragma unroll 4
        for (int d = 0; d < 128; d++) a = fmaf(wf[d] * y[d], w3[(size_t)d * 128 + e], a);
        v = a;
    }
    int src = k >> 7, ksl = (k >> 4) & 7, kr = k & 15;
    int t = (kr >> 1) & 3, hk = (kr >> 3) & 1, hl = kr & 1;
    int nq = e >> 5, np = (e >> 4) & 1, he = (e >> 3) & 1, g = e & 7;
    int idx4 = ((((src * 8 + ksl) * 4 + t) * 2 + np) * 4 + nq) * 8 + g;
    g_W2h[l][(size_t)idx4 * 8 + (hk + 2 * he) * 2 + hl] = __float2half_rn(v);
}

// ---------------------------------------------------------------------------
__global__ void __launch_bounds__(NT) gnn(
    const float* __restrict__ r, const float* __restrict__ Rn,
    const float* __restrict__ ws, const float* __restrict__ wa,
    const float* __restrict__ bu, float* __restrict__ out)
{
    extern __shared__ __align__(16) float sm[];
    __half* smh = (__half*)sm;
    unsigned* smu = (unsigned*)sm;
    const int b = blockIdx.x, tid = threadIdx.x, w = tid >> 5, ln = tid & 31;
    const int g = ln >> 2, t = ln & 3;
    // GEMM2 / epilogue mapping: warp = (rt2, nq)
    const int rt2 = w >> 2, nq = w & 3, ibase = rt2 * 16 + g;
    // GEMM1 mapping: warp = (jblk, wm, wd2)
    const int jblk = w & 1, wm = (w >> 1) & 1, wd2 = w >> 2;
    const float DEL = 4.0f / 7.0f;
    float S[7];
    #pragma unroll
    for (int k = 0; k < 7; k++) S[k] = expf(-DEL * DEL * (float)(2 * k + 1));

    if (tid < 192) { int i = tid / 3, c = tid % 3; sm[O_R + i * 4 + c] = r[((size_t)b * 64 + i) * 3 + c]; }
    __syncthreads();

    // ---- x0: raw staging (ZSQ..ZAQ) + XQ/X0Q fp16 quads + XT fp16 ----
    for (int p = tid; p < 1024; p += NT) {
        int i = p >> 4, n = p & 15;
        float dx = sm[O_R + i * 4]     - Rn[((size_t)b * 16 + n) * 3];
        float dy = sm[O_R + i * 4 + 1] - Rn[((size_t)b * 16 + n) * 3 + 1];
        float dz = sm[O_R + i * 4 + 2] - Rn[((size_t)b * 16 + n) * 3 + 2];
        float d2 = fmaf(dx, dx, fmaf(dy, dy, dz * dz)) + 1e-12f;
        float ft = __expf(-d2), q = __expf(2.f * DEL * sqrtf(d2));
        float v[8];
        #pragma unroll
        for (int f = 0; f < 8; f++) { v[f] = ft; if (f < 7) ft = ft * q * S[f]; }
        #pragma unroll
        for (int f = 0; f < 8; f++) sm[O_ZSQ + i * 128 + n * 8 + f] = v[f];
        // XQ/X0Q: 4 packed half2 per panel
        int hi = (i >> 3) & 1;
        #pragma unroll
        for (int tp = 0; tp < 4; tp++) {
            unsigned uv = h2u(v[2 * tp], v[2 * tp + 1]);
            int fidx = (((i >> 4) * 8 + (n >> 1)) * 32 + (i & 7) * 4 + tp) * 4 + hi + 2 * (n & 1);
            smu[O_XQ + fidx]  = uv;
            smu[O_X0Q + fidx] = uv;
        }
        // XT: 8 u16
        int jb = i >> 5, ksj = (i >> 4) & 1, jrr = i & 15;
        int tj = (jrr >> 1) & 3, hj = (jrr >> 3) & 1, hl = i & 1;
        #pragma unroll
        for (int f = 0; f < 8; f++) {
            int fidx = (((jb * 2 + ksj) * 8 + (n >> 1)) * 32 + f * 4 + tj) * 4 + hj + 2 * (n & 1);
            smh[(O_XT + fidx) * 2 + hl] = __float2half_rn(v[f]);
        }
    }
    // ---- ee features -> g_fqh quads: task per warp (qd, wm2, ksf) ----
    {
        int qd = w >> 2, wm2 = (w >> 1) & 1, ksf = w & 1;
        int iblk = qd >> 1, jb = qd & 1;
        int i0 = iblk * 32 + wm2 * 16 + g;
        int j0 = jb * 32 + ksf * 16;
        int jv[4] = {j0 + 2 * t, j0 + 2 * t + 1, j0 + 2 * t + 8, j0 + 2 * t + 9};
        float ftv[8], qqv[8];
        #pragma unroll
        for (int a = 0; a < 2; a++)
            #pragma unroll
            for (int c = 0; c < 4; c++) {
                int ii = i0 + a * 8, jj = jv[c];
                float dx = sm[O_R + ii * 4]     - sm[O_R + jj * 4];
                float dy = sm[O_R + ii * 4 + 1] - sm[O_R + jj * 4 + 1];
                float dz = sm[O_R + ii * 4 + 2] - sm[O_R + jj * 4 + 2];
                float d2 = fmaf(dx, dx, fmaf(dy, dy, dz * dz)) + 1e-12f;
                int idx = a * 4 + c;
                ftv[idx] = (ii == jj) ? 0.f : __expf(-d2);
                qqv[idx] = __expf(2.f * DEL * sqrtf(d2));
            }
        uint4* gb4 = (uint4*)g_fqh[b];
        #pragma unroll
        for (int f = 0; f < 8; f++) {
            uint4 uq;
            uq.x = h2u(ftv[0], ftv[1]);   // row lo, k-lo
            uq.y = h2u(ftv[4], ftv[5]);   // row hi, k-lo
            uq.z = h2u(ftv[2], ftv[3]);   // row lo, k-hi
            uq.w = h2u(ftv[6], ftv[7]);   // row hi, k-hi
            gb4[((((qd * 8 + f) * 2 + wm2) * 2 + ksf) * 32) + g * 4 + t] = uq;
            if (f < 7) {
                #pragma unroll
                for (int u = 0; u < 8; u++) ftv[u] = ftv[u] * qqv[u] * S[f];
            }
        }
    }
    __syncthreads();

    // ---- raw x residual into registers (16 outputs per thread) ----
    float xf[16];
    {
        const float* st = sm + O_ZSQ;
        #pragma unroll
        for (int nt = 0; nt < 4; nt++) {
            int e = nq * 32 + nt * 8 + 2 * t;
            xf[nt * 4 + 0] = st[ibase * 128 + e];
            xf[nt * 4 + 1] = st[ibase * 128 + e + 1];
            xf[nt * 4 + 2] = st[(ibase + 8) * 128 + e];
            xf[nt * 4 + 3] = st[(ibase + 8) * 128 + e + 1];
        }
    }
    __syncthreads();   // staging reads done before GEMM1 overwrites ZSQ/ZAQ

    const uint4* sm16 = (const uint4*)sm;   // (float index/4 = uint4 index)

    for (int l = 0; l < 3; l++) {
        for (int p = tid; p < 2048; p += NT)
            sm[O_WE + p] = (p < 1024) ? ws[l * 1024 + p] : wa[l * 1024 + p - 1024];
        __syncthreads();

        // ===== GEMM1: warp covers d-width 32, both iblk quadrants =====
        {
            uint4 Bf[2][2];
            #pragma unroll
            for (int ks = 0; ks < 2; ks++)
                #pragma unroll
                for (int np = 0; np < 2; np++)
                    Bf[ks][np] = sm16[(O_XT >> 2) +
                        ((jblk * 2 + ks) * 8 + wd2 * 2 + np) * 32 + ln];

            const uint4* gfq4 = (const uint4*)g_fqh[b];
            #pragma unroll 1
            for (int qi = 0; qi < 2; qi++) {
                const int iblk = qi, q = iblk * 2 + jblk, same = (iblk == jblk);
                float z[4][4];
                #pragma unroll
                for (int nt = 0; nt < 4; nt++)
                    #pragma unroll
                    for (int c = 0; c < 4; c++) z[nt][c] = 0.f;
                const int weo = O_WE + (same ? 0 : 1024);

                #pragma unroll 2
                for (int f = 0; f < 8; f++) {
                    float tf[4][4];
                    #pragma unroll
                    for (int nt = 0; nt < 4; nt++)
                        #pragma unroll
                        for (int c = 0; c < 4; c++) tf[nt][c] = 0.f;
                    #pragma unroll
                    for (int ks = 0; ks < 2; ks++) {
                        uint4 av = gfq4[(((q * 8 + f) * 2 + wm) * 2 + ks) * 32 + ln];
                        unsigned a[4] = {av.x, av.y, av.z, av.w};
                        #pragma unroll
                        for (int np = 0; np < 2; np++) {
                            mma16(tf[np * 2 + 0], a, Bf[ks][np].x, Bf[ks][np].y);
                            mma16(tf[np * 2 + 1], a, Bf[ks][np].z, Bf[ks][np].w);
                        }
                    }
                    #pragma unroll
                    for (int nt = 0; nt < 4; nt++) {
                        float2 wv = *(const float2*)&sm[weo + f * 128 + wd2 * 32 + nt * 8 + 2 * t];
                        z[nt][0] = fmaf(wv.x, tf[nt][0], z[nt][0]);
                        z[nt][1] = fmaf(wv.y, tf[nt][1], z[nt][1]);
                        z[nt][2] = fmaf(wv.x, tf[nt][2], z[nt][2]);
                        z[nt][3] = fmaf(wv.y, tf[nt][3], z[nt][3]);
                    }
                }
                const int zo = (same ? O_ZSQ : O_ZAQ);
                const int i16 = iblk * 2 + wm;
                #pragma unroll
                for (int nt = 0; nt < 4; nt++) {
                    int np = nt >> 1, dh = nt & 1;
                    int base = zo + ((i16 * 8 + (wd2 * 2 + np)) * 32 + g * 4 + t) * 4 + 2 * dh;
                    uint2 uv = make_uint2(h2u(z[nt][0], z[nt][1]), h2u(z[nt][2], z[nt][3]));
                    *(uint2*)&sm[base] = uv;
                }
            }
        }
        __syncthreads();

        // ===== GEMM2: K=512, warp covers N=32 (4 mma chains) =====
        float acc2[4][4];
        #pragma unroll
        for (int nt = 0; nt < 4; nt++)
            #pragma unroll
            for (int c = 0; c < 4; c++) acc2[nt][c] = 0.f;

        #pragma unroll 1
        for (int src = 0; src < 4; src++) {
            const int ap16 = ((src == 0) ? O_XQ : (src == 1) ? O_ZSQ : (src == 2) ? O_ZAQ : O_X0Q) >> 2;
            const uint4* w2q4 = (const uint4*)g_W2h[l] + src * 2048;
            #pragma unroll 4
            for (int ks = 0; ks < 8; ks++) {
                uint4 aq = sm16[ap16 + (rt2 * 8 + ks) * 32 + ln];
                unsigned a[4] = {aq.x, aq.y, aq.z, aq.w};
                uint4 b0 = w2q4[(((ks * 4 + t) * 2 + 0) * 4 + nq) * 8 + g];
                uint4 b1 = w2q4[(((ks * 4 + t) * 2 + 1) * 4 + nq) * 8 + g];
                mma16(acc2[0], a, b0.x, b0.y);
                mma16(acc2[1], a, b0.z, b0.w);
                mma16(acc2[2], a, b1.x, b1.y);
                mma16(acc2[3], a, b1.z, b1.w);
            }
        }
        __syncthreads();

        // ===== epilogue: 16 outputs per thread =====
        #pragma unroll
        for (int nt = 0; nt < 4; nt++) {
            int e = nq * 32 + nt * 8 + 2 * t;
            float b0v = bu[l * 128 + e], b1v = bu[l * 128 + e + 1];
            float n00 = xf[nt * 4 + 0] + tanhf(acc2[nt][0] + b0v);
            float n01 = xf[nt * 4 + 1] + tanhf(acc2[nt][1] + b1v);
            float n10 = xf[nt * 4 + 2] + tanhf(acc2[nt][2] + b0v);
            float n11 = xf[nt * 4 + 3] + tanhf(acc2[nt][3] + b1v);
            xf[nt * 4 + 0] = n00; xf[nt * 4 + 1] = n01;
            xf[nt * 4 + 2] = n10; xf[nt * 4 + 3] = n11;
            if (l < 2) {
                // XQ panel: float2 of half2 (rows ibase, ibase+8)
                int ks = nq * 2 + (nt >> 1);
                int base = O_XQ + ((rt2 * 8 + ks) * 32 + g * 4 + t) * 4 + 2 * (nt & 1);
                *(uint2*)&sm[base] = make_uint2(h2u(n00, n01), h2u(n10, n11));
                // XT panel: 4 u16 (2 rows x 2 e-values)
                int jb = rt2 >> 1, ksj = rt2 & 1, tj = (g >> 1) & 3, hl = g & 1;
                #pragma unroll
                for (int k01 = 0; k01 < 2; k01++) {
                    int ee = e + k01;
                    int fb = (((jb * 2 + ksj) * 8 + (ee >> 4)) * 32 + (ee & 7) * 4 + tj) * 4
                           + 2 * ((ee >> 3) & 1);
                    float vlo = k01 ? n01 : n00, vhi = k01 ? n11 : n10;
                    smh[(O_XT + fb + 0) * 2 + hl] = __float2half_rn(vlo);
                    smh[(O_XT + fb + 1) * 2 + hl] = __float2half_rn(vhi);
                }
            } else {
                out[((size_t)b * 64 + ibase) * 128 + e]         = n00;
                out[((size_t)b * 64 + ibase) * 128 + e + 1]     = n01;
                out[((size_t)b * 64 + ibase + 8) * 128 + e]     = n10;
                out[((size_t)b * 64 + ibase + 8) * 128 + e + 1] = n11;
            }
        }
        __syncthreads();
    }
}

extern "C" void kernel_launch(void* const* d_in, const int* in_sizes, int n_in,
                              void* d_out, int out_size)
{
    const float* r  = (const float*)d_in[0];
    const float* Rn = (const float*)d_in[1];
    const float* et = (const float*)d_in[2];
    const float* ws = (const float*)d_in[3];
    const float* wa = (const float*)d_in[4];
    const float* wn = (const float*)d_in[5];
    const float* wu = (const float*)d_in[6];
    const float* bu = (const float*)d_in[7];
    const int*   at = (const int*)d_in[8];
    float* out = (float*)d_out;

    const int smem = SMF * (int)sizeof(float);   // 91,136 B
    cudaFuncSetAttribute(gnn, cudaFuncAttributeMaxDynamicSharedMemorySize, smem);
    prep<<<dim3(512, 3), 128>>>(et, at, wn, wu);
    gnn<<<512, NT, smem>>>(r, Rn, ws, wa, bu, out);
}

// round 16
// speedup vs baseline: 3.8555x; 1.4056x over previous
#include <cuda_runtime.h>
#include <cuda_fp16.h>
#include <math.h>
#include <stdint.h>

#define NT 512
// ---- smem float offsets ----
#define O_XQ   0       // x   fp16 quads  4096 floats
#define O_X0Q  4096    // x0  4096
#define O_ZSQ  8192    // z_s 4096  (ZSQ..ZAQ doubles as raw-x0 staging [i*128+k])
#define O_ZAQ  12288   // z_a 4096
#define O_XT   16384   // x^T fp16 4096
#define O_WE   20480   // we_same[8][128]+we_anti[8][128]+bias[128] fp32 = 2176
#define O_R    22656   // positions [64][4] = 256
#define O_FEAT 22912   // feat fp16 quads: 4096 uint4 = 16384 floats
#define O_W2S  39296   // W2 staging: 2048 uint4 = 8192 floats
#define SMF    47488   // 189,952 B

__device__ __half g_W2h[3][65536];     // W2 fp16 quads, bank-swizzled ((g+2t)&7)

static __device__ __forceinline__ unsigned h2u(float a, float b) {
    __half2 h = __floats2half2_rn(a, b);
    return *(unsigned*)&h;
}
static __device__ __forceinline__ void mma16(float* d, const unsigned* a, unsigned b0, unsigned b1) {
    asm volatile("mma.sync.aligned.m16n8k16.row.col.f32.f16.f16.f32 "
                 "{%0,%1,%2,%3},{%4,%5,%6,%7},{%8,%9},{%0,%1,%2,%3};"
                 : "+f"(d[0]), "+f"(d[1]), "+f"(d[2]), "+f"(d[3])
                 : "r"(a[0]), "r"(a[1]), "r"(a[2]), "r"(a[3]), "r"(b0), "r"(b1));
}

// ---------------------------------------------------------------------------
__global__ void prep(const float* __restrict__ et, const int* __restrict__ at,
                     const float* __restrict__ wn, const float* __restrict__ wu)
{
    int k = blockIdx.x, l = blockIdx.y, e = threadIdx.x;
    float v;
    if (k < 384) {
        v = wu[((size_t)l * 512 + k) * 128 + e];
    } else {
        int k2 = k - 384, n = k2 >> 3, f = k2 & 7;
        const float* y  = et + at[n] * 128;
        const float* wf = wn + (l * 8 + f) * 128;
        const float* w3 = wu + ((size_t)l * 512 + 384) * 128;
        float a = 0.f;
        #pragma unroll 4
        for (int d = 0; d < 128; d++) a = fmaf(wf[d] * y[d], w3[(size_t)d * 128 + e], a);
        v = a;
    }
    int src = k >> 7, ksl = (k >> 4) & 7, kr = k & 15;
    int t = (kr >> 1) & 3, hk = (kr >> 3) & 1, hl = kr & 1;
    int nq = e >> 5, np = (e >> 4) & 1, he = (e >> 3) & 1, g = e & 7;
    int gs = (g + 2 * t) & 7;    // bank swizzle for staged LDS.128
    int idx4 = ((((src * 8 + ksl) * 4 + t) * 2 + np) * 4 + nq) * 8 + gs;
    g_W2h[l][(size_t)idx4 * 8 + (hk + 2 * he) * 2 + hl] = __float2half_rn(v);
}

// ---------------------------------------------------------------------------
__global__ void __launch_bounds__(NT) gnn(
    const float* __restrict__ r, const float* __restrict__ Rn,
    const float* __restrict__ ws, const float* __restrict__ wa,
    const float* __restrict__ bu, float* __restrict__ out)
{
    extern __shared__ __align__(16) float sm[];
    __half* smh = (__half*)sm;
    unsigned* smu = (unsigned*)sm;
    uint4* sm16w = (uint4*)sm;
    const uint4* sm16 = (const uint4*)sm;
    const int b = blockIdx.x, tid = threadIdx.x, w = tid >> 5, ln = tid & 31;
    const int g = ln >> 2, t = ln & 3;
    const int gs = (g + 2 * t) & 7;
    // GEMM2 / epilogue mapping: warp = (rt2, nq)
    const int rt2 = w >> 2, nq = w & 3, ibase = rt2 * 16 + g;
    // GEMM1 mapping: warp = (jblk, wm, wd2)
    const int jblk = w & 1, wm = (w >> 1) & 1, wd2 = w >> 2;
    const float DEL = 4.0f / 7.0f;
    float S[7];
    #pragma unroll
    for (int k = 0; k < 7; k++) S[k] = expf(-DEL * DEL * (float)(2 * k + 1));

    if (tid < 192) { int i = tid / 3, c = tid % 3; sm[O_R + i * 4 + c] = r[((size_t)b * 64 + i) * 3 + c]; }
    __syncthreads();

    // ---- x0: raw staging (ZSQ..ZAQ) + XQ/X0Q fp16 quads + XT fp16 ----
    for (int p = tid; p < 1024; p += NT) {
        int i = p >> 4, n = p & 15;
        float dx = sm[O_R + i * 4]     - Rn[((size_t)b * 16 + n) * 3];
        float dy = sm[O_R + i * 4 + 1] - Rn[((size_t)b * 16 + n) * 3 + 1];
        float dz = sm[O_R + i * 4 + 2] - Rn[((size_t)b * 16 + n) * 3 + 2];
        float d2 = fmaf(dx, dx, fmaf(dy, dy, dz * dz)) + 1e-12f;
        float ft = __expf(-d2), q = __expf(2.f * DEL * sqrtf(d2));
        float v[8];
        #pragma unroll
        for (int f = 0; f < 8; f++) { v[f] = ft; if (f < 7) ft = ft * q * S[f]; }
        #pragma unroll
        for (int f = 0; f < 8; f++) sm[O_ZSQ + i * 128 + n * 8 + f] = v[f];
        int hi = (i >> 3) & 1;
        #pragma unroll
        for (int tp = 0; tp < 4; tp++) {
            unsigned uv = h2u(v[2 * tp], v[2 * tp + 1]);
            int fidx = (((i >> 4) * 8 + (n >> 1)) * 32 + (i & 7) * 4 + tp) * 4 + hi + 2 * (n & 1);
            smu[O_XQ + fidx]  = uv;
            smu[O_X0Q + fidx] = uv;
        }
        int jb = i >> 5, ksj = (i >> 4) & 1, jrr = i & 15;
        int tj = (jrr >> 1) & 3, hj = (jrr >> 3) & 1, hl = i & 1;
        #pragma unroll
        for (int f = 0; f < 8; f++) {
            int fidx = (((jb * 2 + ksj) * 8 + (n >> 1)) * 32 + f * 4 + tj) * 4 + hj + 2 * (n & 1);
            smh[(O_XT + fidx) * 2 + hl] = __float2half_rn(v[f]);
        }
    }
    // ---- ee features -> smem feat quads (no global round-trip) ----
    {
        int qd = w >> 2, wm2 = (w >> 1) & 1, ksf = w & 1;
        int iblk = qd >> 1, jb = qd & 1;
        int i0 = iblk * 32 + wm2 * 16 + g;
        int j0 = jb * 32 + ksf * 16;
        int jv[4] = {j0 + 2 * t, j0 + 2 * t + 1, j0 + 2 * t + 8, j0 + 2 * t + 9};
        float ftv[8], qqv[8];
        #pragma unroll
        for (int a = 0; a < 2; a++)
            #pragma unroll
            for (int c = 0; c < 4; c++) {
                int ii = i0 + a * 8, jj = jv[c];
                float dx = sm[O_R + ii * 4]     - sm[O_R + jj * 4];
                float dy = sm[O_R + ii * 4 + 1] - sm[O_R + jj * 4 + 1];
                float dz = sm[O_R + ii * 4 + 2] - sm[O_R + jj * 4 + 2];
                float d2 = fmaf(dx, dx, fmaf(dy, dy, dz * dz)) + 1e-12f;
                int idx = a * 4 + c;
                ftv[idx] = (ii == jj) ? 0.f : __expf(-d2);
                qqv[idx] = __expf(2.f * DEL * sqrtf(d2));
            }
        #pragma unroll
        for (int f = 0; f < 8; f++) {
            uint4 uq;
            uq.x = h2u(ftv[0], ftv[1]);
            uq.y = h2u(ftv[4], ftv[5]);
            uq.z = h2u(ftv[2], ftv[3]);
            uq.w = h2u(ftv[6], ftv[7]);
            sm16w[(O_FEAT >> 2) + ((((qd * 8 + f) * 2 + wm2) * 2 + ksf) * 32) + g * 4 + t] = uq;
            if (f < 7) {
                #pragma unroll
                for (int u = 0; u < 8; u++) ftv[u] = ftv[u] * qqv[u] * S[f];
            }
        }
    }
    __syncthreads();

    // ---- raw x residual into registers ----
    float xf[16];
    {
        const float* st = sm + O_ZSQ;
        #pragma unroll
        for (int nt = 0; nt < 4; nt++) {
            int e = nq * 32 + nt * 8 + 2 * t;
            xf[nt * 4 + 0] = st[ibase * 128 + e];
            xf[nt * 4 + 1] = st[ibase * 128 + e + 1];
            xf[nt * 4 + 2] = st[(ibase + 8) * 128 + e];
            xf[nt * 4 + 3] = st[(ibase + 8) * 128 + e + 1];
        }
    }
    __syncthreads();

    for (int l = 0; l < 3; l++) {
        const uint4* w2g = (const uint4*)g_W2h[l];
        uint4 wreg[4];
        // prefetch src0 W2 (latency hidden under we-staging + GEMM1)
        #pragma unroll
        for (int u = 0; u < 4; u++) wreg[u] = w2g[u * 512 + tid];
        // stage we + bias
        for (int p = tid; p < 2176; p += NT)
            sm[O_WE + p] = (p < 1024) ? ws[l * 1024 + p]
                         : (p < 2048) ? wa[l * 1024 + p - 1024]
                                      : bu[l * 128 + p - 2048];
        __syncthreads();

        // ===== GEMM1: feat (smem) x x^T (smem), warp covers d-width 32 =====
        {
            uint4 Bf[2][2];
            #pragma unroll
            for (int ks = 0; ks < 2; ks++)
                #pragma unroll
                for (int np = 0; np < 2; np++)
                    Bf[ks][np] = sm16[(O_XT >> 2) +
                        ((jblk * 2 + ks) * 8 + wd2 * 2 + np) * 32 + ln];

            #pragma unroll 1
            for (int qi = 0; qi < 2; qi++) {
                const int iblk = qi, q = iblk * 2 + jblk, same = (iblk == jblk);
                float z[4][4];
                #pragma unroll
                for (int nt = 0; nt < 4; nt++)
                    #pragma unroll
                    for (int c = 0; c < 4; c++) z[nt][c] = 0.f;
                const int weo = O_WE + (same ? 0 : 1024);

                #pragma unroll 2
                for (int f = 0; f < 8; f++) {
                    float tf[4][4];
                    #pragma unroll
                    for (int nt = 0; nt < 4; nt++)
                        #pragma unroll
                        for (int c = 0; c < 4; c++) tf[nt][c] = 0.f;
                    #pragma unroll
                    for (int ks = 0; ks < 2; ks++) {
                        uint4 av = sm16[(O_FEAT >> 2) +
                            (((q * 8 + f) * 2 + wm) * 2 + ks) * 32 + ln];
                        unsigned a[4] = {av.x, av.y, av.z, av.w};
                        #pragma unroll
                        for (int np = 0; np < 2; np++) {
                            mma16(tf[np * 2 + 0], a, Bf[ks][np].x, Bf[ks][np].y);
                            mma16(tf[np * 2 + 1], a, Bf[ks][np].z, Bf[ks][np].w);
                        }
                    }
                    #pragma unroll
                    for (int nt = 0; nt < 4; nt++) {
                        float2 wv = *(const float2*)&sm[weo + f * 128 + wd2 * 32 + nt * 8 + 2 * t];
                        z[nt][0] = fmaf(wv.x, tf[nt][0], z[nt][0]);
                        z[nt][1] = fmaf(wv.y, tf[nt][1], z[nt][1]);
                        z[nt][2] = fmaf(wv.x, tf[nt][2], z[nt][2]);
                        z[nt][3] = fmaf(wv.y, tf[nt][3], z[nt][3]);
                    }
                }
                const int zo = (same ? O_ZSQ : O_ZAQ);
                const int i16 = iblk * 2 + wm;
                #pragma unroll
                for (int nt = 0; nt < 4; nt++) {
                    int np = nt >> 1, dh = nt & 1;
                    int base = zo + ((i16 * 8 + (wd2 * 2 + np)) * 32 + g * 4 + t) * 4 + 2 * dh;
                    *(uint2*)&sm[base] =
                        make_uint2(h2u(z[nt][0], z[nt][1]), h2u(z[nt][2], z[nt][3]));
                }
            }
        }
        __syncthreads();

        // ===== GEMM2: K=512, W2 pipelined global->reg->smem =====
        float acc2[4][4];
        #pragma unroll
        for (int nt = 0; nt < 4; nt++)
            #pragma unroll
            for (int c = 0; c < 4; c++) acc2[nt][c] = 0.f;

        uint4* w2s = sm16w + (O_W2S >> 2);
        #pragma unroll 1
        for (int src = 0; src < 4; src++) {
            #pragma unroll
            for (int u = 0; u < 4; u++) w2s[u * 512 + tid] = wreg[u];
            __syncthreads();
            if (src < 3) {
                #pragma unroll
                for (int u = 0; u < 4; u++) wreg[u] = w2g[(src + 1) * 2048 + u * 512 + tid];
            }
            const int ap16 = ((src == 0) ? O_XQ : (src == 1) ? O_ZSQ
                            : (src == 2) ? O_ZAQ : O_X0Q) >> 2;
            #pragma unroll
            for (int ks = 0; ks < 8; ks++) {
                uint4 aq = sm16[ap16 + (rt2 * 8 + ks) * 32 + ln];
                unsigned a[4] = {aq.x, aq.y, aq.z, aq.w};
                uint4 b0 = w2s[(((ks * 4 + t) * 2 + 0) * 4 + nq) * 8 + gs];
                uint4 b1 = w2s[(((ks * 4 + t) * 2 + 1) * 4 + nq) * 8 + gs];
                mma16(acc2[0], a, b0.x, b0.y);
                mma16(acc2[1], a, b0.z, b0.w);
                mma16(acc2[2], a, b1.x, b1.y);
                mma16(acc2[3], a, b1.z, b1.w);
            }
            __syncthreads();
        }

        // ===== epilogue: 16 outputs per thread =====
        #pragma unroll
        for (int nt = 0; nt < 4; nt++) {
            int e = nq * 32 + nt * 8 + 2 * t;
            float b0v = sm[O_WE + 2048 + e], b1v = sm[O_WE + 2048 + e + 1];
            float n00 = xf[nt * 4 + 0] + tanhf(acc2[nt][0] + b0v);
            float n01 = xf[nt * 4 + 1] + tanhf(acc2[nt][1] + b1v);
            float n10 = xf[nt * 4 + 2] + tanhf(acc2[nt][2] + b0v);
            float n11 = xf[nt * 4 + 3] + tanhf(acc2[nt][3] + b1v);
            xf[nt * 4 + 0] = n00; xf[nt * 4 + 1] = n01;
            xf[nt * 4 + 2] = n10; xf[nt * 4 + 3] = n11;
            if (l < 2) {
                int ks = nq * 2 + (nt >> 1);
                int base = O_XQ + ((rt2 * 8 + ks) * 32 + g * 4 + t) * 4 + 2 * (nt & 1);
                *(uint2*)&sm[base] = make_uint2(h2u(n00, n01), h2u(n10, n11));
                int jb = rt2 >> 1, ksj = rt2 & 1, tj = (g >> 1) & 3, hl = g & 1;
                #pragma unroll
                for (int k01 = 0; k01 < 2; k01++) {
                    int ee = e + k01;
                    int fb = (((jb * 2 + ksj) * 8 + (ee >> 4)) * 32 + (ee & 7) * 4 + tj) * 4
                           + 2 * ((ee >> 3) & 1);
                    float vlo = k01 ? n01 : n00, vhi = k01 ? n11 : n10;
                    smh[(O_XT + fb + 0) * 2 + hl] = __float2half_rn(vlo);
                    smh[(O_XT + fb + 1) * 2 + hl] = __float2half_rn(vhi);
                }
            } else {
                out[((size_t)b * 64 + ibase) * 128 + e]         = n00;
                out[((size_t)b * 64 + ibase) * 128 + e + 1]     = n01;
                out[((size_t)b * 64 + ibase + 8) * 128 + e]     = n10;
                out[((size_t)b * 64 + ibase + 8) * 128 + e + 1] = n11;
            }
        }
        __syncthreads();
    }
}

extern "C" void kernel_launch(void* const* d_in, const int* in_sizes, int n_in,
                              void* d_out, int out_size)
{
    const float* r  = (const float*)d_in[0];
    const float* Rn = (const float*)d_in[1];
    const float* et = (const float*)d_in[2];
    const float* ws = (const float*)d_in[3];
    const float* wa = (const float*)d_in[4];
    const float* wn = (const float*)d_in[5];
    const float* wu = (const float*)d_in[6];
    const float* bu = (const float*)d_in[7];
    const int*   at = (const int*)d_in[8];
    float* out = (float*)d_out;

    const int smem = SMF * (int)sizeof(float);   // 189,952 B
    cudaFuncSetAttribute(gnn, cudaFuncAttributeMaxDynamicSharedMemorySize, smem);
    prep<<<dim3(512, 3), 128>>>(et, at, wn, wu);
    gnn<<<512, NT, smem>>>(r, Rn, ws, wa, bu, out);
}

// round 17
// speedup vs baseline: 3.9641x; 1.0282x over previous
#include <cuda_runtime.h>
#include <cuda_fp16.h>
#include <math.h>
#include <stdint.h>

#define NT 512
// ---- smem float offsets ----
#define O_XQ   0       // x   fp16 quads  4096 floats
#define O_X0Q  4096    // x0  4096
#define O_ZSQ  8192    // z_s 4096  (ZSQ..ZAQ doubles as raw-x0 staging [i*128+k])
#define O_ZAQ  12288   // z_a 4096
#define O_XT   16384   // x^T fp16 4096
#define O_WE   20480   // we_same[8][128]+we_anti[8][128]+bias[128] fp32 = 2176
#define O_R    22656   // positions [64][4] = 256
#define O_FEAT 22912   // feat fp16 quads: 4096 uint4 = 16384 floats
#define O_W2S  39296   // W2 staging x2 buffers: 4096 uint4 = 16384 floats
#define SMF    55680   // 222,720 B

__device__ __half g_W2h[3][65536];     // W2 fp16 quads, bank-swizzled ((g+2t)&7)

static __device__ __forceinline__ unsigned h2u(float a, float b) {
    __half2 h = __floats2half2_rn(a, b);
    return *(unsigned*)&h;
}
static __device__ __forceinline__ float tanh_fast(float x) {
    float e = __expf(2.f * x);
    return 1.f - __fdividef(2.f, e + 1.f);
}
static __device__ __forceinline__ void mma16(float* d, const unsigned* a, unsigned b0, unsigned b1) {
    asm volatile("mma.sync.aligned.m16n8k16.row.col.f32.f16.f16.f32 "
                 "{%0,%1,%2,%3},{%4,%5,%6,%7},{%8,%9},{%0,%1,%2,%3};"
                 : "+f"(d[0]), "+f"(d[1]), "+f"(d[2]), "+f"(d[3])
                 : "r"(a[0]), "r"(a[1]), "r"(a[2]), "r"(a[3]), "r"(b0), "r"(b1));
}

// ---------------------------------------------------------------------------
__global__ void prep(const float* __restrict__ et, const int* __restrict__ at,
                     const float* __restrict__ wn, const float* __restrict__ wu)
{
    int k = blockIdx.x, l = blockIdx.y, e = threadIdx.x;
    float v;
    if (k < 384) {
        v = wu[((size_t)l * 512 + k) * 128 + e];
    } else {
        int k2 = k - 384, n = k2 >> 3, f = k2 & 7;
        const float* y  = et + at[n] * 128;
        const float* wf = wn + (l * 8 + f) * 128;
        const float* w3 = wu + ((size_t)l * 512 + 384) * 128;
        float a = 0.f;
        #pragma unroll 4
        for (int d = 0; d < 128; d++) a = fmaf(wf[d] * y[d], w3[(size_t)d * 128 + e], a);
        v = a;
    }
    int src = k >> 7, ksl = (k >> 4) & 7, kr = k & 15;
    int t = (kr >> 1) & 3, hk = (kr >> 3) & 1, hl = kr & 1;
    int nq = e >> 5, np = (e >> 4) & 1, he = (e >> 3) & 1, g = e & 7;
    int gs = (g + 2 * t) & 7;    // bank swizzle for staged LDS.128
    int idx4 = ((((src * 8 + ksl) * 4 + t) * 2 + np) * 4 + nq) * 8 + gs;
    g_W2h[l][(size_t)idx4 * 8 + (hk + 2 * he) * 2 + hl] = __float2half_rn(v);
}

// ---------------------------------------------------------------------------
__global__ void __launch_bounds__(NT) gnn(
    const float* __restrict__ r, const float* __restrict__ Rn,
    const float* __restrict__ ws, const float* __restrict__ wa,
    const float* __restrict__ bu, float* __restrict__ out)
{
    extern __shared__ __align__(16) float sm[];
    __half* smh = (__half*)sm;
    unsigned* smu = (unsigned*)sm;
    uint4* sm16w = (uint4*)sm;
    const uint4* sm16 = (const uint4*)sm;
    const int b = blockIdx.x, tid = threadIdx.x, w = tid >> 5, ln = tid & 31;
    const int g = ln >> 2, t = ln & 3;
    const int gs = (g + 2 * t) & 7;
    // GEMM2 / epilogue mapping: warp = (rt2, nq)
    const int rt2 = w >> 2, nq = w & 3, ibase = rt2 * 16 + g;
    // GEMM1 mapping: warp = (jblk, wm, wd2)
    const int jblk = w & 1, wm = (w >> 1) & 1, wd2 = w >> 2;
    const float DEL = 4.0f / 7.0f;
    float S[7];
    #pragma unroll
    for (int k = 0; k < 7; k++) S[k] = expf(-DEL * DEL * (float)(2 * k + 1));

    if (tid < 192) { int i = tid / 3, c = tid % 3; sm[O_R + i * 4 + c] = r[((size_t)b * 64 + i) * 3 + c]; }
    __syncthreads();

    // ---- x0: raw staging (ZSQ..ZAQ) + XQ/X0Q fp16 quads + XT fp16 ----
    for (int p = tid; p < 1024; p += NT) {
        int i = p >> 4, n = p & 15;
        float dx = sm[O_R + i * 4]     - Rn[((size_t)b * 16 + n) * 3];
        float dy = sm[O_R + i * 4 + 1] - Rn[((size_t)b * 16 + n) * 3 + 1];
        float dz = sm[O_R + i * 4 + 2] - Rn[((size_t)b * 16 + n) * 3 + 2];
        float d2 = fmaf(dx, dx, fmaf(dy, dy, dz * dz)) + 1e-12f;
        float ft = __expf(-d2), q = __expf(2.f * DEL * sqrtf(d2));
        float v[8];
        #pragma unroll
        for (int f = 0; f < 8; f++) { v[f] = ft; if (f < 7) ft = ft * q * S[f]; }
        #pragma unroll
        for (int f = 0; f < 8; f++) sm[O_ZSQ + i * 128 + n * 8 + f] = v[f];
        int hi = (i >> 3) & 1;
        #pragma unroll
        for (int tp = 0; tp < 4; tp++) {
            unsigned uv = h2u(v[2 * tp], v[2 * tp + 1]);
            int fidx = (((i >> 4) * 8 + (n >> 1)) * 32 + (i & 7) * 4 + tp) * 4 + hi + 2 * (n & 1);
            smu[O_XQ + fidx]  = uv;
            smu[O_X0Q + fidx] = uv;
        }
        int jb = i >> 5, ksj = (i >> 4) & 1, jrr = i & 15;
        int tj = (jrr >> 1) & 3, hj = (jrr >> 3) & 1, hl = i & 1;
        #pragma unroll
        for (int f = 0; f < 8; f++) {
            int fidx = (((jb * 2 + ksj) * 8 + (n >> 1)) * 32 + f * 4 + tj) * 4 + hj + 2 * (n & 1);
            smh[(O_XT + fidx) * 2 + hl] = __float2half_rn(v[f]);
        }
    }
    // ---- ee features -> smem feat quads ----
    {
        int qd = w >> 2, wm2 = (w >> 1) & 1, ksf = w & 1;
        int iblk = qd >> 1, jb = qd & 1;
        int i0 = iblk * 32 + wm2 * 16 + g;
        int j0 = jb * 32 + ksf * 16;
        int jv[4] = {j0 + 2 * t, j0 + 2 * t + 1, j0 + 2 * t + 8, j0 + 2 * t + 9};
        float ftv[8], qqv[8];
        #pragma unroll
        for (int a = 0; a < 2; a++)
            #pragma unroll
            for (int c = 0; c < 4; c++) {
                int ii = i0 + a * 8, jj = jv[c];
                float dx = sm[O_R + ii * 4]     - sm[O_R + jj * 4];
                float dy = sm[O_R + ii * 4 + 1] - sm[O_R + jj * 4 + 1];
                float dz = sm[O_R + ii * 4 + 2] - sm[O_R + jj * 4 + 2];
                float d2 = fmaf(dx, dx, fmaf(dy, dy, dz * dz)) + 1e-12f;
                int idx = a * 4 + c;
                ftv[idx] = (ii == jj) ? 0.f : __expf(-d2);
                qqv[idx] = __expf(2.f * DEL * sqrtf(d2));
            }
        #pragma unroll
        for (int f = 0; f < 8; f++) {
            uint4 uq;
            uq.x = h2u(ftv[0], ftv[1]);
            uq.y = h2u(ftv[4], ftv[5]);
            uq.z = h2u(ftv[2], ftv[3]);
            uq.w = h2u(ftv[6], ftv[7]);
            sm16w[(O_FEAT >> 2) + ((((qd * 8 + f) * 2 + wm2) * 2 + ksf) * 32) + g * 4 + t] = uq;
            if (f < 7) {
                #pragma unroll
                for (int u = 0; u < 8; u++) ftv[u] = ftv[u] * qqv[u] * S[f];
            }
        }
    }
    __syncthreads();

    // ---- raw x residual into registers ----
    float xf[16];
    {
        const float* st = sm + O_ZSQ;
        #pragma unroll
        for (int nt = 0; nt < 4; nt++) {
            int e = nq * 32 + nt * 8 + 2 * t;
            xf[nt * 4 + 0] = st[ibase * 128 + e];
            xf[nt * 4 + 1] = st[ibase * 128 + e + 1];
            xf[nt * 4 + 2] = st[(ibase + 8) * 128 + e];
            xf[nt * 4 + 3] = st[(ibase + 8) * 128 + e + 1];
        }
    }
    __syncthreads();

    for (int l = 0; l < 3; l++) {
        const uint4* w2g = (const uint4*)g_W2h[l];
        uint4 wreg[4];
        // prefetch src0 W2 (latency hidden under we-staging + GEMM1)
        #pragma unroll
        for (int u = 0; u < 4; u++) wreg[u] = w2g[u * 512 + tid];
        // stage we + bias
        for (int p = tid; p < 2176; p += NT)
            sm[O_WE + p] = (p < 1024) ? ws[l * 1024 + p]
                         : (p < 2048) ? wa[l * 1024 + p - 1024]
                                      : bu[l * 128 + p - 2048];
        __syncthreads();

        // ===== GEMM1: feat (smem) x x^T (smem), warp covers d-width 32 =====
        {
            uint4 Bf[2][2];
            #pragma unroll
            for (int ks = 0; ks < 2; ks++)
                #pragma unroll
                for (int np = 0; np < 2; np++)
                    Bf[ks][np] = sm16[(O_XT >> 2) +
                        ((jblk * 2 + ks) * 8 + wd2 * 2 + np) * 32 + ln];

            #pragma unroll 1
            for (int qi = 0; qi < 2; qi++) {
                const int iblk = qi, q = iblk * 2 + jblk, same = (iblk == jblk);
                float z[4][4];
                #pragma unroll
                for (int nt = 0; nt < 4; nt++)
                    #pragma unroll
                    for (int c = 0; c < 4; c++) z[nt][c] = 0.f;
                const int weo = O_WE + (same ? 0 : 1024);

                #pragma unroll 2
                for (int f = 0; f < 8; f++) {
                    float tf[4][4];
                    #pragma unroll
                    for (int nt = 0; nt < 4; nt++)
                        #pragma unroll
                        for (int c = 0; c < 4; c++) tf[nt][c] = 0.f;
                    #pragma unroll
                    for (int ks = 0; ks < 2; ks++) {
                        uint4 av = sm16[(O_FEAT >> 2) +
                            (((q * 8 + f) * 2 + wm) * 2 + ks) * 32 + ln];
                        unsigned a[4] = {av.x, av.y, av.z, av.w};
                        #pragma unroll
                        for (int np = 0; np < 2; np++) {
                            mma16(tf[np * 2 + 0], a, Bf[ks][np].x, Bf[ks][np].y);
                            mma16(tf[np * 2 + 1], a, Bf[ks][np].z, Bf[ks][np].w);
                        }
                    }
                    #pragma unroll
                    for (int nt = 0; nt < 4; nt++) {
                        float2 wv = *(const float2*)&sm[weo + f * 128 + wd2 * 32 + nt * 8 + 2 * t];
                        z[nt][0] = fmaf(wv.x, tf[nt][0], z[nt][0]);
                        z[nt][1] = fmaf(wv.y, tf[nt][1], z[nt][1]);
                        z[nt][2] = fmaf(wv.x, tf[nt][2], z[nt][2]);
                        z[nt][3] = fmaf(wv.y, tf[nt][3], z[nt][3]);
                    }
                }
                const int zo = (same ? O_ZSQ : O_ZAQ);
                const int i16 = iblk * 2 + wm;
                #pragma unroll
                for (int nt = 0; nt < 4; nt++) {
                    int np = nt >> 1, dh = nt & 1;
                    int base = zo + ((i16 * 8 + (wd2 * 2 + np)) * 32 + g * 4 + t) * 4 + 2 * dh;
                    *(uint2*)&sm[base] =
                        make_uint2(h2u(z[nt][0], z[nt][1]), h2u(z[nt][2], z[nt][3]));
                }
            }
        }
        // (no barrier here: GEMM2 src0's barrier orders z-stores before their reads)

        // ===== GEMM2: K=512, double-buffered W2 staging, 1 sync per src =====
        float acc2[4][4];
        #pragma unroll
        for (int nt = 0; nt < 4; nt++)
            #pragma unroll
            for (int c = 0; c < 4; c++) acc2[nt][c] = 0.f;

        uint4* w2s = sm16w + (O_W2S >> 2);
        #pragma unroll 1
        for (int src = 0; src < 4; src++) {
            uint4* buf = w2s + (src & 1) * 2048;
            #pragma unroll
            for (int u = 0; u < 4; u++) buf[u * 512 + tid] = wreg[u];
            if (src < 3) {
                #pragma unroll
                for (int u = 0; u < 4; u++) wreg[u] = w2g[(src + 1) * 2048 + u * 512 + tid];
            }
            __syncthreads();
            const int ap16 = ((src == 0) ? O_XQ : (src == 1) ? O_ZSQ
                            : (src == 2) ? O_ZAQ : O_X0Q) >> 2;
            #pragma unroll
            for (int ks = 0; ks < 8; ks++) {
                uint4 aq = sm16[ap16 + (rt2 * 8 + ks) * 32 + ln];
                unsigned a[4] = {aq.x, aq.y, aq.z, aq.w};
                uint4 b0 = buf[(((ks * 4 + t) * 2 + 0) * 4 + nq) * 8 + gs];
                uint4 b1 = buf[(((ks * 4 + t) * 2 + 1) * 4 + nq) * 8 + gs];
                mma16(acc2[0], a, b0.x, b0.y);
                mma16(acc2[1], a, b0.z, b0.w);
                mma16(acc2[2], a, b1.x, b1.y);
                mma16(acc2[3], a, b1.z, b1.w);
            }
        }

        // ===== epilogue: 16 outputs per thread (fast tanh) =====
        #pragma unroll
        for (int nt = 0; nt < 4; nt++) {
            int e = nq * 32 + nt * 8 + 2 * t;
            float b0v = sm[O_WE + 2048 + e], b1v = sm[O_WE + 2048 + e + 1];
            float n00 = xf[nt * 4 + 0] + tanh_fast(acc2[nt][0] + b0v);
            float n01 = xf[nt * 4 + 1] + tanh_fast(acc2[nt][1] + b1v);
            float n10 = xf[nt * 4 + 2] + tanh_fast(acc2[nt][2] + b0v);
            float n11 = xf[nt * 4 + 3] + tanh_fast(acc2[nt][3] + b1v);
            xf[nt * 4 + 0] = n00; xf[nt * 4 + 1] = n01;
            xf[nt * 4 + 2] = n10; xf[nt * 4 + 3] = n11;
            if (l < 2) {
                int ks = nq * 2 + (nt >> 1);
                int base = O_XQ + ((rt2 * 8 + ks) * 32 + g * 4 + t) * 4 + 2 * (nt & 1);
                *(uint2*)&sm[base] = make_uint2(h2u(n00, n01), h2u(n10, n11));
                int jb = rt2 >> 1, ksj = rt2 & 1, tj = (g >> 1) & 3, hl = g & 1;
                #pragma unroll
                for (int k01 = 0; k01 < 2; k01++) {
                    int ee = e + k01;
                    int fb = (((jb * 2 + ksj) * 8 + (ee >> 4)) * 32 + (ee & 7) * 4 + tj) * 4
                           + 2 * ((ee >> 3) & 1);
                    float vlo = k01 ? n01 : n00, vhi = k01 ? n11 : n10;
                    smh[(O_XT + fb + 0) * 2 + hl] = __float2half_rn(vlo);
                    smh[(O_XT + fb + 1) * 2 + hl] = __float2half_rn(vhi);
                }
            } else {
                out[((size_t)b * 64 + ibase) * 128 + e]         = n00;
                out[((size_t)b * 64 + ibase) * 128 + e + 1]     = n01;
                out[((size_t)b * 64 + ibase + 8) * 128 + e]     = n10;
                out[((size_t)b * 64 + ibase + 8) * 128 + e + 1] = n11;
            }
        }
        __syncthreads();
    }
}

extern "C" void kernel_launch(void* const* d_in, const int* in_sizes, int n_in,
                              void* d_out, int out_size)
{
    const float* r  = (const float*)d_in[0];
    const float* Rn = (const float*)d_in[1];
    const float* et = (const float*)d_in[2];
    const float* ws = (const float*)d_in[3];
    const float* wa = (const float*)d_in[4];
    const float* wn = (const float*)d_in[5];
    const float* wu = (const float*)d_in[6];
    const float* bu = (const float*)d_in[7];
    const int*   at = (const int*)d_in[8];
    float* out = (float*)d_out;

    const int smem = SMF * (int)sizeof(float);   // 222,720 B
    cudaFuncSetAttribute(gnn, cudaFuncAttributeMaxDynamicSharedMemorySize, smem);
    prep<<<dim3(512, 3), 128>>>(et, at, wn, wu);
    gnn<<<512, NT, smem>>>(r, Rn, ws, wa, bu, out);
}